// round 13
// baseline (speedup 1.0000x reference)
#include <cuda_runtime.h>
#include <cuda_fp16.h>
#include <cstdint>

// Problem constants: B=16, T=16 (Tm1=15), K=32, Do=128, H=256
#define NBT   240
#define NOBJ  32
#define DOBJ  128
#define NH    256
#define MROWS (NBT * NOBJ)   // 7680
#define NTILES 1920          // 8 mtiles x 240 bt
#define GRID2  148

// Scratch (fp16 U / V' = V + b1)
__device__ __align__(16) __half g_Uh[MROWS * NH];
__device__ __align__(16) __half g_Vh[MROWS * NH];
__device__ float g_S[MROWS];
// fp16 SW128-swizzled images (image = 128 rows x 64 halfs = 16KB)
__device__ __align__(16) unsigned char g_W2h[2 * 4 * 16384];   // [nh][4 k-imgs]
__device__ __align__(16) unsigned char g_Xh [60 * 2 * 16384];  // [mtile][2 k-imgs]
__device__ __align__(16) unsigned char g_W1h[4 * 2 * 16384];   // [ntile][2 k-imgs]

__device__ __forceinline__ uint32_t sw128(uint32_t off) { return off ^ ((off >> 3) & 0x70); }
__device__ __forceinline__ uint32_t smem_u32(const void* p) {
    uint32_t a;
    asm("{ .reg .u64 t; cvta.to.shared.u64 t, %1; cvt.u32.u64 %0, t; }" : "=r"(a) : "l"(p));
    return a;
}

#define LDSM_X4(r0, r1, r2, r3, addr) \
    asm volatile("ldmatrix.sync.aligned.m8n8.x4.shared.b16 {%0,%1,%2,%3}, [%4];" \
        : "=r"(r0), "=r"(r1), "=r"(r2), "=r"(r3) : "r"(addr))
#define MMA16816(d, a, b) \
    asm volatile("mma.sync.aligned.m16n8k16.row.col.f32.f16.f16.f32 " \
        "{%0,%1,%2,%3}, {%4,%5,%6,%7}, {%8,%9}, {%0,%1,%2,%3};" \
        : "+f"((d)[0]), "+f"((d)[1]), "+f"((d)[2]), "+f"((d)[3]) \
        : "r"((a)[0]), "r"((a)[1]), "r"((a)[2]), "r"((a)[3]), "r"((b)[0]), "r"((b)[1]))
#define CP_ASYNC16(dst, src) \
    asm volatile("cp.async.cg.shared.global [%0], [%1], 16;" :: "r"((uint32_t)(dst)), "l"(src))
#define CP_COMMIT() asm volatile("cp.async.commit_group;" ::: "memory")
#define CP_WAIT0()  asm volatile("cp.async.wait_group 0;" ::: "memory")

__device__ __forceinline__ uint32_t packh2(float x0, float x1) {
    __half2 h = __float22half2_rn(make_float2(x0, x1));
    return reinterpret_cast<uint32_t&>(h);
}
__device__ __forceinline__ uint32_t hadd_relu(uint32_t a, uint32_t b) {
    __half2 x = __hadd2(*reinterpret_cast<__half2*>(&a), *reinterpret_cast<__half2*>(&b));
    x = __hmax2(x, __float2half2_rn(0.0f));
    return reinterpret_cast<uint32_t&>(x);
}

#define VSTRIDE 280   // halfs; 560B rows, 16B-aligned, LDS.128 conflict-free

// ---------------------------------------------------------------------------
// conv_x: gather X (rows t>=1) -> fp16 swizzled images; fused clipped row sums.
// ---------------------------------------------------------------------------
__global__ void conv_x_kernel(const float* __restrict__ X) {
    int idx = blockIdx.x * 256 + threadIdx.x;
    int m  = idx >> 4;
    int g  = idx & 15;
    int kh = g >> 3, k8 = (g & 7) * 8;
    int bt = m >> 5, i = m & 31;
    int b  = bt / 15, t = bt - b * 15;
    const float* src = X + (size_t)((b * 16 + t + 1) * 32 + i) * DOBJ + kh * 64 + k8;
    float4 v0 = *(const float4*)(src);
    float4 v1 = *(const float4*)(src + 4);
    uint4 w;
    w.x = packh2(v0.x, v0.y); w.y = packh2(v0.z, v0.w);
    w.z = packh2(v1.x, v1.y); w.w = packh2(v1.z, v1.w);
    *(uint4*)(g_Xh + (m >> 7) * 32768 + kh * 16384 + sw128((uint32_t)((m & 127) * 128 + k8 * 2))) = w;
    float ssum = v0.x + v0.y + v0.z + v0.w + v1.x + v1.y + v1.z + v1.w;
#pragma unroll
    for (int off = 8; off >= 1; off >>= 1)
        ssum += __shfl_xor_sync(0xFFFFFFFF, ssum, off, 32);
    if (g == 0) g_S[m] = fminf(fmaxf(ssum, 0.0f), 1.0f);
}

// ---------------------------------------------------------------------------
// prep_w: W1 AND W2 -> fp16 swizzled images (merged)
// ---------------------------------------------------------------------------
__global__ void prep_w_kernel(const float* __restrict__ W1, const float* __restrict__ W2) {
    int idx = blockIdx.x * 256 + threadIdx.x;   // 0..16383
    if (idx < 8192) {
        int op = idx >> 4;
        int g  = idx & 15;
        int kh = g >> 3, k8 = (g & 7) * 8;
        const float* src = W1 + (op & 255) * 256 + ((op >= 256) ? 128 : 0) + kh * 64 + k8;
        float4 v0 = *(const float4*)(src);
        float4 v1 = *(const float4*)(src + 4);
        uint4 w;
        w.x = packh2(v0.x, v0.y); w.y = packh2(v0.z, v0.w);
        w.z = packh2(v1.x, v1.y); w.w = packh2(v1.z, v1.w);
        int ntile = op >> 7, n = op & 127;
        *(uint4*)(g_W1h + ntile * 32768 + kh * 16384 + sw128((uint32_t)(n * 128 + k8 * 2))) = w;
    } else {
        int j = idx - 8192;
        int n = j >> 5;
        int g = j & 31;
        int c = g >> 3;
        int k8 = (g & 7) * 8;
        const float* src = W2 + n * 256 + c * 64 + k8;
        float4 v0 = *(const float4*)(src);
        float4 v1 = *(const float4*)(src + 4);
        uint4 w;
        w.x = packh2(v0.x, v0.y); w.y = packh2(v0.z, v0.w);
        w.z = packh2(v1.x, v1.y); w.w = packh2(v1.z, v1.w);
        *(uint4*)(g_W2h + (n >> 7) * 65536 + c * 16384 + sw128((uint32_t)((n & 127) * 128 + k8 * 2))) = w;
    }
}

// ---------------------------------------------------------------------------
// gemm1 via mma: grid (ntile 4, mtile 60), 256 thr. Epilogue -> fp16 U/V'.
// ---------------------------------------------------------------------------
#define G1_B    32768
#define G1_BIAS 65536
#define G1_SMEM 66048

__global__ __launch_bounds__(256, 2)
void gemm1_mma(const float* __restrict__ b1) {
    extern __shared__ __align__(1024) unsigned char smem[];
    const int tid = threadIdx.x, lane = tid & 31, wid = tid >> 5;
    const int ntile = blockIdx.x, mtile = blockIdx.y;
    const uint32_t sA = smem_u32(smem);
    const uint32_t sB = sA + G1_B;

    const uint4* gA = (const uint4*)(g_Xh)  + (size_t)mtile * 2048;
    const uint4* gB = (const uint4*)(g_W1h) + (size_t)ntile * 2048;
#pragma unroll
    for (int q = 0; q < 8; q++) {
        int s = tid + q * 256;
        CP_ASYNC16(sA + s * 16, gA + s);
        CP_ASYNC16(sB + s * 16, gB + s);
    }
    CP_COMMIT();
    if (ntile >= 2 && tid < 32)
        ((float4*)(smem + G1_BIAS))[tid] = ((const float4*)(b1 + (ntile - 2) * 128))[tid];
    CP_WAIT0();
    __syncthreads();

    float acc[2][8][4];
#pragma unroll
    for (int mt = 0; mt < 2; mt++)
#pragma unroll
        for (int nt = 0; nt < 8; nt++)
#pragma unroll
            for (int q = 0; q < 4; q++) acc[mt][nt][q] = 0.0f;

    const int m0w = (wid & 3) * 32;
    const int n0w = (wid >> 2) * 64;

#pragma unroll
    for (int ks = 0; ks < 8; ks++) {
        const int img = ks >> 2, kk = ks & 3;
        uint32_t afr[2][4], bfr[8][2];
        int abyte = kk * 32 + ((lane >> 4) << 4);
        int arow  = m0w + (lane & 15);
        uint32_t ab = sA + img * 16384;
        LDSM_X4(afr[0][0], afr[0][1], afr[0][2], afr[0][3], ab + sw128((uint32_t)(arow * 128 + abyte)));
        LDSM_X4(afr[1][0], afr[1][1], afr[1][2], afr[1][3], ab + sw128((uint32_t)((arow + 16) * 128 + abyte)));
        int nr  = n0w + ((lane >> 4) << 3) + (lane & 7);
        int kb2 = kk * 32 + (((lane >> 3) & 1) << 4);
        uint32_t bb = sB + img * 16384;
#pragma unroll
        for (int ntp = 0; ntp < 4; ntp++) {
            LDSM_X4(bfr[ntp * 2][0], bfr[ntp * 2][1],
                    bfr[ntp * 2 + 1][0], bfr[ntp * 2 + 1][1],
                    bb + sw128((uint32_t)((nr + ntp * 16) * 128 + kb2)));
        }
#pragma unroll
        for (int mt = 0; mt < 2; mt++)
#pragma unroll
            for (int nt = 0; nt < 8; nt++)
                MMA16816(acc[mt][nt], afr[mt], bfr[nt]);
    }

    const float* sBias = (const float*)(smem + G1_BIAS);
#pragma unroll
    for (int mt = 0; mt < 2; mt++) {
#pragma unroll
        for (int hp = 0; hp < 2; hp++) {
            int rl = m0w + mt * 16 + hp * 8 + (lane >> 2);
            int m  = mtile * 128 + rl;
#pragma unroll
            for (int nt = 0; nt < 8; nt++) {
                int nc = n0w + nt * 8 + (lane & 3) * 2;
                float ox = acc[mt][nt][hp * 2];
                float oy = acc[mt][nt][hp * 2 + 1];
                if (ntile < 2) {
                    *(uint32_t*)(g_Uh + (size_t)m * NH + ntile * 128 + nc) = packh2(ox, oy);
                } else {
                    *(uint32_t*)(g_Vh + (size_t)m * NH + (ntile - 2) * 128 + nc) =
                        packh2(ox + sBias[nc], oy + sBias[nc + 1]);
                }
            }
        }
    }
}

// ---------------------------------------------------------------------------
// gemm2 PERSISTENT: grid 148, 512 thr (16 warps, 64x32 warp tiles).
// R11 flow; burst split into 2 M-passes (acc 32 regs each) so ptxas can
// software-pipeline LDSMs. Epilogue per pass.
// ---------------------------------------------------------------------------
#define OFF_A   0
#define OFF_B   65536
#define OFF_V   196608   // 32 x VSTRIDE halfs = 17920
#define OFF_U   214528   // 4 x 256 halfs = 2048
#define OFF_B2  216576   // 256 fp32 = 1024
#define SMEM2   217600

__global__ __launch_bounds__(512, 1)
void gemm2_mma(const float* __restrict__ b2, float* __restrict__ out_e,
               float* __restrict__ out_a) {
    extern __shared__ __align__(1024) unsigned char smem[];
    const int tid = threadIdx.x, lane = tid & 31, wid = tid >> 5;
    const int cta = blockIdx.x;

    __half* sVh = (__half*)(smem + OFF_V);
    __half* sUh = (__half*)(smem + OFF_U);
    float*  sb2 = (float*)(smem + OFF_B2);

    const uint32_t sA = smem_u32(smem);
    const uint32_t sB = sA + OFF_B;
    const uint32_t sV = sA + OFF_V;
    const uint32_t sU = sA + OFF_U;

    // ---- one-time: whole W2h (128KB) + b2 ----
    {
        const uint4* gB = (const uint4*)(g_W2h);
#pragma unroll
        for (int q = 0; q < 16; q++) {
            int s = tid + q * 512;
            CP_ASYNC16(sB + s * 16, gB + s);
        }
        if (tid < 64) ((float4*)sb2)[tid] = ((const float4*)b2)[tid];
    }
    // ---- prefetch V/U for first tile ----
    int tile = cta;
    {
        int bt = tile >> 3, mtile = tile & 7;
        const uint4* Vg = (const uint4*)(g_Vh + (size_t)bt * NOBJ * NH);
#pragma unroll
        for (int q = 0; q < 2; q++) {
            int fidx = tid + q * 512;
            int row = fidx >> 5, col8 = (fidx & 31) * 8;
            CP_ASYNC16(sV + (row * VSTRIDE + col8) * 2, Vg + fidx);
        }
        if (tid < 128)
            CP_ASYNC16(sU + tid * 16,
                       (const uint4*)(g_Uh + ((size_t)bt * NOBJ + mtile * 4) * NH) + tid);
    }
    CP_COMMIT();
    CP_WAIT0();
    __syncthreads();

    const int m0w = (wid & 1) * 64;           // 2 warps over M=128
    const int n0w = (wid >> 1) * 32;          // 8 warps over N=256
    const uint32_t bblk = sB + (uint32_t)(n0w >> 7) * 65536;
    const int nloc = n0w & 127;
    const int r   = tid & 127;
    const int kq  = tid >> 7;                 // 0..3: this thread's A image

    for (; tile < NTILES; tile += GRID2) {
        const int bt = tile >> 3, mtile = tile & 7;

        // ---- generate A: each thread one row-slice of one image ----
        {
            const __half* u = sUh + (r >> 5) * 256 + kq * 64;
            const __half* v = sVh + (r & 31) * VSTRIDE + kq * 64;
            uint32_t abase = sA + kq * 16384;
#pragma unroll
            for (int g = 0; g < 4; g++) {
                uint4 ua0 = *(const uint4*)(u + g * 16);
                uint4 ua1 = *(const uint4*)(u + g * 16 + 8);
                uint4 va0 = *(const uint4*)(v + g * 16);
                uint4 va1 = *(const uint4*)(v + g * 16 + 8);
                uint4 w0, w1;
                w0.x = hadd_relu(ua0.x, va0.x); w0.y = hadd_relu(ua0.y, va0.y);
                w0.z = hadd_relu(ua0.z, va0.z); w0.w = hadd_relu(ua0.w, va0.w);
                w1.x = hadd_relu(ua1.x, va1.x); w1.y = hadd_relu(ua1.y, va1.y);
                w1.z = hadd_relu(ua1.z, va1.z); w1.w = hadd_relu(ua1.w, va1.w);
                asm volatile("st.shared.v4.b32 [%0], {%1,%2,%3,%4};"
                    :: "r"(abase + sw128((uint32_t)(r * 128 + g * 32))),
                       "r"(w0.x), "r"(w0.y), "r"(w0.z), "r"(w0.w) : "memory");
                asm volatile("st.shared.v4.b32 [%0], {%1,%2,%3,%4};"
                    :: "r"(abase + sw128((uint32_t)(r * 128 + g * 32 + 16))),
                       "r"(w1.x), "r"(w1.y), "r"(w1.z), "r"(w1.w) : "memory");
            }
        }
        __syncthreads();   // A visible; V/U reads done

        // ---- prefetch NEXT tile's V/U (overlaps bursts + epilogues) ----
        const int ntile2 = tile + GRID2;
        if (ntile2 < NTILES) {
            int nbt = ntile2 >> 3, nmt = ntile2 & 7;
            const uint4* Vg = (const uint4*)(g_Vh + (size_t)nbt * NOBJ * NH);
#pragma unroll
            for (int q = 0; q < 2; q++) {
                int fidx = tid + q * 512;
                int row = fidx >> 5, col8 = (fidx & 31) * 8;
                CP_ASYNC16(sV + (row * VSTRIDE + col8) * 2, Vg + fidx);
            }
            if (tid < 128)
                CP_ASYNC16(sU + tid * 16,
                           (const uint4*)(g_Uh + ((size_t)nbt * NOBJ + nmt * 4) * NH) + tid);
            CP_COMMIT();
        }

        // ---- burst: 2 M-passes (acc=32 regs each; ptxas pipelines LDSM) ----
        const size_t rowbase = (size_t)bt * 1024 + mtile * 128;
#pragma unroll
        for (int pass = 0; pass < 2; pass++) {
            const int mtb = pass * 2;
            float acc[2][4][4];
#pragma unroll
            for (int mt = 0; mt < 2; mt++)
#pragma unroll
                for (int nt = 0; nt < 4; nt++)
#pragma unroll
                    for (int q = 0; q < 4; q++) acc[mt][nt][q] = 0.0f;

#pragma unroll
            for (int ks = 0; ks < 16; ks++) {
                const int img = ks >> 2, kk = ks & 3;
                uint32_t afr[2][4], bfr[4][2];
                int abyte = kk * 32 + ((lane >> 4) << 4);
                int arow  = m0w + (mtb << 4) + (lane & 15);
                uint32_t ab = sA + img * 16384;
                LDSM_X4(afr[0][0], afr[0][1], afr[0][2], afr[0][3],
                        ab + sw128((uint32_t)(arow * 128 + abyte)));
                LDSM_X4(afr[1][0], afr[1][1], afr[1][2], afr[1][3],
                        ab + sw128((uint32_t)((arow + 16) * 128 + abyte)));
                int nr  = nloc + ((lane >> 4) << 3) + (lane & 7);
                int kb2 = kk * 32 + (((lane >> 3) & 1) << 4);
                uint32_t bb = bblk + img * 16384;
#pragma unroll
                for (int ntp = 0; ntp < 2; ntp++)
                    LDSM_X4(bfr[ntp * 2][0], bfr[ntp * 2][1],
                            bfr[ntp * 2 + 1][0], bfr[ntp * 2 + 1][1],
                            bb + sw128((uint32_t)((nr + ntp * 16) * 128 + kb2)));
#pragma unroll
                for (int mt = 0; mt < 2; mt++)
#pragma unroll
                    for (int nt = 0; nt < 4; nt++)
                        MMA16816(acc[mt][nt], afr[mt], bfr[nt]);
            }

            // epilogue for this pass's 2 M-subtiles
#pragma unroll
            for (int mt = 0; mt < 2; mt++) {
#pragma unroll
                for (int hp = 0; hp < 2; hp++) {
                    int rl = m0w + (mtb + mt) * 16 + hp * 8 + (lane >> 2);
                    float* dst = out_e + (rowbase + rl) * 256 + (lane & 3) * 2;
#pragma unroll
                    for (int nt = 0; nt < 4; nt++) {
                        int nc = n0w + nt * 8 + (lane & 3) * 2;
                        float2 o;
                        o.x = fmaxf(acc[mt][nt][hp * 2]     + sb2[nc],     0.0f);
                        o.y = fmaxf(acc[mt][nt][hp * 2 + 1] + sb2[nc + 1], 0.0f);
                        *(float2*)(dst + n0w + nt * 8) = o;
                    }
                }
            }
        }

        CP_WAIT0();
        __syncthreads();   // next V/U in smem; A safe to overwrite
    }

    // ---- tail: all_is_obj (folded aux) ----
    for (int bt = cta; bt < NBT; bt += GRID2) {
        const int t = bt - (bt / 15) * 15;
        const float tc = (float)(t + 1);
        const float* sRow = g_S + bt * 32;
#pragma unroll
        for (int q = 0; q < 2; q++) {
            int p = tid + q * 512;
            float v = sRow[p >> 5] * sRow[p & 31] * tc;
            out_a[(size_t)bt * 1024 + p] = fminf(fmaxf(v, 0.0f), 1.0f);
        }
    }
}

// ---------------------------------------------------------------------------
extern "C" void kernel_launch(void* const* d_in, const int* in_sizes, int n_in,
                              void* d_out, int out_size) {
    const float* X  = (const float*)d_in[0];
    const float* W1 = (const float*)d_in[1];
    const float* b1 = (const float*)d_in[2];
    const float* W2 = (const float*)d_in[3];
    const float* b2 = (const float*)d_in[4];
    float* out = (float*)d_out;

    size_t e_elems = (size_t)out_size - (size_t)NBT * 1024;

    cudaFuncSetAttribute(gemm1_mma, cudaFuncAttributeMaxDynamicSharedMemorySize, G1_SMEM);
    cudaFuncSetAttribute(gemm2_mma, cudaFuncAttributeMaxDynamicSharedMemorySize, SMEM2);

    conv_x_kernel<<<480, 256>>>(X);                       // launch 1
    prep_w_kernel<<<64, 256>>>(W1, W2);                   // launch 2
    gemm1_mma<<<dim3(4, 60), 256, G1_SMEM>>>(b1);         // launch 3
    gemm2_mma<<<GRID2, 512, SMEM2>>>(b2, out, out + e_elems);  // launch 4 (profiled)
}

// round 14
// speedup vs baseline: 2.4489x; 2.4489x over previous
#include <cuda_runtime.h>
#include <cuda_fp16.h>
#include <cstdint>

// Problem constants: B=16, T=16 (Tm1=15), K=32, Do=128, H=256
#define NBT   240
#define NOBJ  32
#define DOBJ  128
#define NH    256
#define MROWS (NBT * NOBJ)   // 7680
#define NTILES 1920          // 8 mtiles x 240 bt
#define GRID2  148

// Scratch (fp16 U / V' = V + b1)
__device__ __align__(16) __half g_Uh[MROWS * NH];
__device__ __align__(16) __half g_Vh[MROWS * NH];
__device__ float g_S[MROWS];
// fp16 SW128-swizzled images (image = 128 rows x 64 halfs = 16KB)
__device__ __align__(16) unsigned char g_W2h[2 * 4 * 16384];   // [nh][4 k-imgs]
__device__ __align__(16) unsigned char g_Xh [60 * 2 * 16384];  // [mtile][2 k-imgs]
__device__ __align__(16) unsigned char g_W1h[4 * 2 * 16384];   // [ntile][2 k-imgs]

__device__ __forceinline__ uint32_t sw128(uint32_t off) { return off ^ ((off >> 3) & 0x70); }
__device__ __forceinline__ uint32_t smem_u32(const void* p) {
    uint32_t a;
    asm("{ .reg .u64 t; cvta.to.shared.u64 t, %1; cvt.u32.u64 %0, t; }" : "=r"(a) : "l"(p));
    return a;
}

#define LDSM_X4(r0, r1, r2, r3, addr) \
    asm volatile("ldmatrix.sync.aligned.m8n8.x4.shared.b16 {%0,%1,%2,%3}, [%4];" \
        : "=r"(r0), "=r"(r1), "=r"(r2), "=r"(r3) : "r"(addr))
#define MMA16816(d, a, b) \
    asm volatile("mma.sync.aligned.m16n8k16.row.col.f32.f16.f16.f32 " \
        "{%0,%1,%2,%3}, {%4,%5,%6,%7}, {%8,%9}, {%0,%1,%2,%3};" \
        : "+f"((d)[0]), "+f"((d)[1]), "+f"((d)[2]), "+f"((d)[3]) \
        : "r"((a)[0]), "r"((a)[1]), "r"((a)[2]), "r"((a)[3]), "r"((b)[0]), "r"((b)[1]))
#define CP_ASYNC16(dst, src) \
    asm volatile("cp.async.cg.shared.global [%0], [%1], 16;" :: "r"((uint32_t)(dst)), "l"(src))
#define CP_COMMIT() asm volatile("cp.async.commit_group;" ::: "memory")
#define CP_WAIT0()  asm volatile("cp.async.wait_group 0;" ::: "memory")

__device__ __forceinline__ uint32_t packh2(float x0, float x1) {
    __half2 h = __float22half2_rn(make_float2(x0, x1));
    return reinterpret_cast<uint32_t&>(h);
}
__device__ __forceinline__ uint32_t hadd_relu(uint32_t a, uint32_t b) {
    __half2 x = __hadd2(*reinterpret_cast<__half2*>(&a), *reinterpret_cast<__half2*>(&b));
    x = __hmax2(x, __float2half2_rn(0.0f));
    return reinterpret_cast<uint32_t&>(x);
}

#define VSTRIDE 280   // halfs; 560B rows, 16B-aligned, LDS.128 conflict-free

// ---------------------------------------------------------------------------
// conv_x: gather X (rows t>=1) -> fp16 swizzled images; fused clipped row sums.
// ---------------------------------------------------------------------------
__global__ void conv_x_kernel(const float* __restrict__ X) {
    int idx = blockIdx.x * 256 + threadIdx.x;
    int m  = idx >> 4;
    int g  = idx & 15;
    int kh = g >> 3, k8 = (g & 7) * 8;
    int bt = m >> 5, i = m & 31;
    int b  = bt / 15, t = bt - b * 15;
    const float* src = X + (size_t)((b * 16 + t + 1) * 32 + i) * DOBJ + kh * 64 + k8;
    float4 v0 = *(const float4*)(src);
    float4 v1 = *(const float4*)(src + 4);
    uint4 w;
    w.x = packh2(v0.x, v0.y); w.y = packh2(v0.z, v0.w);
    w.z = packh2(v1.x, v1.y); w.w = packh2(v1.z, v1.w);
    *(uint4*)(g_Xh + (m >> 7) * 32768 + kh * 16384 + sw128((uint32_t)((m & 127) * 128 + k8 * 2))) = w;
    float ssum = v0.x + v0.y + v0.z + v0.w + v1.x + v1.y + v1.z + v1.w;
#pragma unroll
    for (int off = 8; off >= 1; off >>= 1)
        ssum += __shfl_xor_sync(0xFFFFFFFF, ssum, off, 32);
    if (g == 0) g_S[m] = fminf(fmaxf(ssum, 0.0f), 1.0f);
}

// ---------------------------------------------------------------------------
// prep_w: W1 AND W2 -> fp16 swizzled images (merged)
// ---------------------------------------------------------------------------
__global__ void prep_w_kernel(const float* __restrict__ W1, const float* __restrict__ W2) {
    int idx = blockIdx.x * 256 + threadIdx.x;   // 0..16383
    if (idx < 8192) {
        int op = idx >> 4;
        int g  = idx & 15;
        int kh = g >> 3, k8 = (g & 7) * 8;
        const float* src = W1 + (op & 255) * 256 + ((op >= 256) ? 128 : 0) + kh * 64 + k8;
        float4 v0 = *(const float4*)(src);
        float4 v1 = *(const float4*)(src + 4);
        uint4 w;
        w.x = packh2(v0.x, v0.y); w.y = packh2(v0.z, v0.w);
        w.z = packh2(v1.x, v1.y); w.w = packh2(v1.z, v1.w);
        int ntile = op >> 7, n = op & 127;
        *(uint4*)(g_W1h + ntile * 32768 + kh * 16384 + sw128((uint32_t)(n * 128 + k8 * 2))) = w;
    } else {
        int j = idx - 8192;
        int n = j >> 5;
        int g = j & 31;
        int c = g >> 3;
        int k8 = (g & 7) * 8;
        const float* src = W2 + n * 256 + c * 64 + k8;
        float4 v0 = *(const float4*)(src);
        float4 v1 = *(const float4*)(src + 4);
        uint4 w;
        w.x = packh2(v0.x, v0.y); w.y = packh2(v0.z, v0.w);
        w.z = packh2(v1.x, v1.y); w.w = packh2(v1.z, v1.w);
        *(uint4*)(g_W2h + (n >> 7) * 65536 + c * 16384 + sw128((uint32_t)((n & 127) * 128 + k8 * 2))) = w;
    }
}

// ---------------------------------------------------------------------------
// gemm1 via mma: grid (ntile 4, mtile 60), 256 thr. Epilogue -> fp16 U/V'.
// ---------------------------------------------------------------------------
#define G1_B    32768
#define G1_BIAS 65536
#define G1_SMEM 66048

__global__ __launch_bounds__(256, 2)
void gemm1_mma(const float* __restrict__ b1) {
    extern __shared__ __align__(1024) unsigned char smem[];
    const int tid = threadIdx.x, lane = tid & 31, wid = tid >> 5;
    const int ntile = blockIdx.x, mtile = blockIdx.y;
    const uint32_t sA = smem_u32(smem);
    const uint32_t sB = sA + G1_B;

    const uint4* gA = (const uint4*)(g_Xh)  + (size_t)mtile * 2048;
    const uint4* gB = (const uint4*)(g_W1h) + (size_t)ntile * 2048;
#pragma unroll
    for (int q = 0; q < 8; q++) {
        int s = tid + q * 256;
        CP_ASYNC16(sA + s * 16, gA + s);
        CP_ASYNC16(sB + s * 16, gB + s);
    }
    CP_COMMIT();
    if (ntile >= 2 && tid < 32)
        ((float4*)(smem + G1_BIAS))[tid] = ((const float4*)(b1 + (ntile - 2) * 128))[tid];
    CP_WAIT0();
    __syncthreads();

    float acc[2][8][4];
#pragma unroll
    for (int mt = 0; mt < 2; mt++)
#pragma unroll
        for (int nt = 0; nt < 8; nt++)
#pragma unroll
            for (int q = 0; q < 4; q++) acc[mt][nt][q] = 0.0f;

    const int m0w = (wid & 3) * 32;
    const int n0w = (wid >> 2) * 64;

#pragma unroll
    for (int ks = 0; ks < 8; ks++) {
        const int img = ks >> 2, kk = ks & 3;
        uint32_t afr[2][4], bfr[8][2];
        int abyte = kk * 32 + ((lane >> 4) << 4);
        int arow  = m0w + (lane & 15);
        uint32_t ab = sA + img * 16384;
        LDSM_X4(afr[0][0], afr[0][1], afr[0][2], afr[0][3], ab + sw128((uint32_t)(arow * 128 + abyte)));
        LDSM_X4(afr[1][0], afr[1][1], afr[1][2], afr[1][3], ab + sw128((uint32_t)((arow + 16) * 128 + abyte)));
        int nr  = n0w + ((lane >> 4) << 3) + (lane & 7);
        int kb2 = kk * 32 + (((lane >> 3) & 1) << 4);
        uint32_t bb = sB + img * 16384;
#pragma unroll
        for (int ntp = 0; ntp < 4; ntp++) {
            LDSM_X4(bfr[ntp * 2][0], bfr[ntp * 2][1],
                    bfr[ntp * 2 + 1][0], bfr[ntp * 2 + 1][1],
                    bb + sw128((uint32_t)((nr + ntp * 16) * 128 + kb2)));
        }
#pragma unroll
        for (int mt = 0; mt < 2; mt++)
#pragma unroll
            for (int nt = 0; nt < 8; nt++)
                MMA16816(acc[mt][nt], afr[mt], bfr[nt]);
    }

    const float* sBias = (const float*)(smem + G1_BIAS);
#pragma unroll
    for (int mt = 0; mt < 2; mt++) {
#pragma unroll
        for (int hp = 0; hp < 2; hp++) {
            int rl = m0w + mt * 16 + hp * 8 + (lane >> 2);
            int m  = mtile * 128 + rl;
#pragma unroll
            for (int nt = 0; nt < 8; nt++) {
                int nc = n0w + nt * 8 + (lane & 3) * 2;
                float ox = acc[mt][nt][hp * 2];
                float oy = acc[mt][nt][hp * 2 + 1];
                if (ntile < 2) {
                    *(uint32_t*)(g_Uh + (size_t)m * NH + ntile * 128 + nc) = packh2(ox, oy);
                } else {
                    *(uint32_t*)(g_Vh + (size_t)m * NH + (ntile - 2) * 128 + nc) =
                        packh2(ox + sBias[nc], oy + sBias[nc + 1]);
                }
            }
        }
    }
}

// ---------------------------------------------------------------------------
// gemm2 PERSISTENT: grid 148, 512 thr (16 warps, 64x32 warp tiles).
// R11 structure exactly; epilogue stores use __stcs (streaming, L2-protect).
// ---------------------------------------------------------------------------
#define OFF_A   0
#define OFF_B   65536
#define OFF_V   196608   // 32 x VSTRIDE halfs = 17920
#define OFF_U   214528   // 4 x 256 halfs = 2048
#define OFF_B2  216576   // 256 fp32 = 1024
#define SMEM2   217600

__global__ __launch_bounds__(512, 1)
void gemm2_mma(const float* __restrict__ b2, float* __restrict__ out_e,
               float* __restrict__ out_a) {
    extern __shared__ __align__(1024) unsigned char smem[];
    const int tid = threadIdx.x, lane = tid & 31, wid = tid >> 5;
    const int cta = blockIdx.x;

    __half* sVh = (__half*)(smem + OFF_V);
    __half* sUh = (__half*)(smem + OFF_U);
    float*  sb2 = (float*)(smem + OFF_B2);

    const uint32_t sA = smem_u32(smem);
    const uint32_t sB = sA + OFF_B;
    const uint32_t sV = sA + OFF_V;
    const uint32_t sU = sA + OFF_U;

    // ---- one-time: whole W2h (128KB) + b2 ----
    {
        const uint4* gB = (const uint4*)(g_W2h);
#pragma unroll
        for (int q = 0; q < 16; q++) {
            int s = tid + q * 512;
            CP_ASYNC16(sB + s * 16, gB + s);
        }
        if (tid < 64) ((float4*)sb2)[tid] = ((const float4*)b2)[tid];
    }
    // ---- prefetch V/U for first tile ----
    int tile = cta;
    {
        int bt = tile >> 3, mtile = tile & 7;
        const uint4* Vg = (const uint4*)(g_Vh + (size_t)bt * NOBJ * NH);
#pragma unroll
        for (int q = 0; q < 2; q++) {
            int fidx = tid + q * 512;
            int row = fidx >> 5, col8 = (fidx & 31) * 8;
            CP_ASYNC16(sV + (row * VSTRIDE + col8) * 2, Vg + fidx);
        }
        if (tid < 128)
            CP_ASYNC16(sU + tid * 16,
                       (const uint4*)(g_Uh + ((size_t)bt * NOBJ + mtile * 4) * NH) + tid);
    }
    CP_COMMIT();
    CP_WAIT0();
    __syncthreads();

    const int m0w = (wid & 1) * 64;           // 2 warps over M=128
    const int n0w = (wid >> 1) * 32;          // 8 warps over N=256
    const uint32_t bblk = sB + (uint32_t)(n0w >> 7) * 65536;
    const int nloc = n0w & 127;
    const int r   = tid & 127;
    const int kq  = tid >> 7;                 // 0..3: this thread's A image

    for (; tile < NTILES; tile += GRID2) {
        const int bt = tile >> 3, mtile = tile & 7;

        // ---- generate A: each thread one row-slice of one image ----
        {
            const __half* u = sUh + (r >> 5) * 256 + kq * 64;
            const __half* v = sVh + (r & 31) * VSTRIDE + kq * 64;
            uint32_t abase = sA + kq * 16384;
#pragma unroll
            for (int g = 0; g < 4; g++) {
                uint4 ua0 = *(const uint4*)(u + g * 16);
                uint4 ua1 = *(const uint4*)(u + g * 16 + 8);
                uint4 va0 = *(const uint4*)(v + g * 16);
                uint4 va1 = *(const uint4*)(v + g * 16 + 8);
                uint4 w0, w1;
                w0.x = hadd_relu(ua0.x, va0.x); w0.y = hadd_relu(ua0.y, va0.y);
                w0.z = hadd_relu(ua0.z, va0.z); w0.w = hadd_relu(ua0.w, va0.w);
                w1.x = hadd_relu(ua1.x, va1.x); w1.y = hadd_relu(ua1.y, va1.y);
                w1.z = hadd_relu(ua1.z, va1.z); w1.w = hadd_relu(ua1.w, va1.w);
                asm volatile("st.shared.v4.b32 [%0], {%1,%2,%3,%4};"
                    :: "r"(abase + sw128((uint32_t)(r * 128 + g * 32))),
                       "r"(w0.x), "r"(w0.y), "r"(w0.z), "r"(w0.w) : "memory");
                asm volatile("st.shared.v4.b32 [%0], {%1,%2,%3,%4};"
                    :: "r"(abase + sw128((uint32_t)(r * 128 + g * 32 + 16))),
                       "r"(w1.x), "r"(w1.y), "r"(w1.z), "r"(w1.w) : "memory");
            }
        }
        __syncthreads();   // A visible; V/U reads done

        // ---- prefetch NEXT tile's V/U (overlaps burst + epilogue) ----
        const int ntile2 = tile + GRID2;
        if (ntile2 < NTILES) {
            int nbt = ntile2 >> 3, nmt = ntile2 & 7;
            const uint4* Vg = (const uint4*)(g_Vh + (size_t)nbt * NOBJ * NH);
#pragma unroll
            for (int q = 0; q < 2; q++) {
                int fidx = tid + q * 512;
                int row = fidx >> 5, col8 = (fidx & 31) * 8;
                CP_ASYNC16(sV + (row * VSTRIDE + col8) * 2, Vg + fidx);
            }
            if (tid < 128)
                CP_ASYNC16(sU + tid * 16,
                           (const uint4*)(g_Uh + ((size_t)nbt * NOBJ + nmt * 4) * NH) + tid);
            CP_COMMIT();
        }

        // ---- MMA burst: 16 k-steps, no syncs. 6 LDSM + 16 HMMA per step ----
        float acc[4][4][4];
#pragma unroll
        for (int mt = 0; mt < 4; mt++)
#pragma unroll
            for (int nt = 0; nt < 4; nt++)
#pragma unroll
                for (int q = 0; q < 4; q++) acc[mt][nt][q] = 0.0f;

#pragma unroll
        for (int ks = 0; ks < 16; ks++) {
            const int img = ks >> 2, kk = ks & 3;
            uint32_t afr[4][4], bfr[4][2];
            int abyte = kk * 32 + ((lane >> 4) << 4);
            int arow  = m0w + (lane & 15);
            uint32_t ab = sA + img * 16384;
#pragma unroll
            for (int mt = 0; mt < 4; mt++)
                LDSM_X4(afr[mt][0], afr[mt][1], afr[mt][2], afr[mt][3],
                        ab + sw128((uint32_t)((arow + mt * 16) * 128 + abyte)));
            int nr  = nloc + ((lane >> 4) << 3) + (lane & 7);
            int kb2 = kk * 32 + (((lane >> 3) & 1) << 4);
            uint32_t bb = bblk + img * 16384;
#pragma unroll
            for (int ntp = 0; ntp < 2; ntp++)
                LDSM_X4(bfr[ntp * 2][0], bfr[ntp * 2][1],
                        bfr[ntp * 2 + 1][0], bfr[ntp * 2 + 1][1],
                        bb + sw128((uint32_t)((nr + ntp * 16) * 128 + kb2)));
#pragma unroll
            for (int mt = 0; mt < 4; mt++)
#pragma unroll
                for (int nt = 0; nt < 4; nt++)
                    MMA16816(acc[mt][nt], afr[mt], bfr[nt]);
        }

        // ---- epilogue: e = relu(acc + b2), streaming stores ----
        const size_t rowbase = (size_t)bt * 1024 + mtile * 128;
#pragma unroll
        for (int mt = 0; mt < 4; mt++) {
#pragma unroll
            for (int hp = 0; hp < 2; hp++) {
                int rl = m0w + mt * 16 + hp * 8 + (lane >> 2);
                float* dst = out_e + (rowbase + rl) * 256 + (lane & 3) * 2;
#pragma unroll
                for (int nt = 0; nt < 4; nt++) {
                    int nc = n0w + nt * 8 + (lane & 3) * 2;
                    float2 o;
                    o.x = fmaxf(acc[mt][nt][hp * 2]     + sb2[nc],     0.0f);
                    o.y = fmaxf(acc[mt][nt][hp * 2 + 1] + sb2[nc + 1], 0.0f);
                    __stcs((float2*)(dst + n0w + nt * 8), o);
                }
            }
        }

        CP_WAIT0();
        __syncthreads();   // next V/U in smem; A safe to overwrite
    }

    // ---- tail: all_is_obj (folded aux) ----
    for (int bt = cta; bt < NBT; bt += GRID2) {
        const int t = bt - (bt / 15) * 15;
        const float tc = (float)(t + 1);
        const float* sRow = g_S + bt * 32;
#pragma unroll
        for (int q = 0; q < 2; q++) {
            int p = tid + q * 512;
            float v = sRow[p >> 5] * sRow[p & 31] * tc;
            out_a[(size_t)bt * 1024 + p] = fminf(fmaxf(v, 0.0f), 1.0f);
        }
    }
}

// ---------------------------------------------------------------------------
extern "C" void kernel_launch(void* const* d_in, const int* in_sizes, int n_in,
                              void* d_out, int out_size) {
    const float* X  = (const float*)d_in[0];
    const float* W1 = (const float*)d_in[1];
    const float* b1 = (const float*)d_in[2];
    const float* W2 = (const float*)d_in[3];
    const float* b2 = (const float*)d_in[4];
    float* out = (float*)d_out;

    size_t e_elems = (size_t)out_size - (size_t)NBT * 1024;

    cudaFuncSetAttribute(gemm1_mma, cudaFuncAttributeMaxDynamicSharedMemorySize, G1_SMEM);
    cudaFuncSetAttribute(gemm2_mma, cudaFuncAttributeMaxDynamicSharedMemorySize, SMEM2);

    conv_x_kernel<<<480, 256>>>(X);                       // launch 1
    prep_w_kernel<<<64, 256>>>(W1, W2);                   // launch 2
    gemm1_mma<<<dim3(4, 60), 256, G1_SMEM>>>(b1);         // launch 3
    gemm2_mma<<<GRID2, 512, SMEM2>>>(b2, out, out + e_elems);  // launch 4 (profiled)
}